// round 16
// baseline (speedup 1.0000x reference)
#include <cuda_runtime.h>
#include <math.h>
#include <stdint.h>

#define Nn   4096
#define Tt   2048
#define Dd   256
#define H1d  128
#define H2d  32
#define NHd  4
#define CAP  96
#define LRELU_ALPHA 0.2f

// ------------------------- scratch (__device__ globals) --------------------
__device__ float g_Wh_c[NHd * Nn * Dd];
__device__ float g_Wh_t[NHd * Tt * Dd];
__device__ float g_f_c[NHd * Nn], g_g_c[NHd * Nn];
__device__ float g_f_t[NHd * Tt], g_g_t[NHd * Tt];
__device__ float g_wa[2 * 2 * NHd * Dd];     // [graph][src/dst][head][d]
__device__ int   g_nbr_c[Nn * CAP];
__device__ float g_val_c[Nn * CAP];
__device__ int   g_cnt_c[Nn];
__device__ int   g_nbr_t[Tt * CAP];
__device__ float g_val_t[Tt * CAP];
__device__ int   g_cnt_t[Tt];
__device__ float g_tmp1[Nn * H1d];
__device__ float g_h1[Nn * H1d];
__device__ float g_tmp2a[Nn * H2d];
__device__ float g_tmp2b[Nn * H2d];
// split-K partial buffers
__device__ float g_P0[2 * Nn * Dd];
__device__ float g_P1[4 * Tt * Dd];
__device__ float g_P2[4 * Nn * Dd];
// raw intermediates (consumers split in-register)
__device__ float g_hcatc[Nn * NHd * Dd];
__device__ float g_hcatt[Tt * NHd * Dd];
__device__ float g_fused[Nn * Dd];
__device__ float g_fusion[Nn * Dd];
// hi/lo planes (weights + gtext + mu)
__device__ float g_gatW_h[NHd * Dd * Dd], g_gatW_l[NHd * Dd * Dd];
__device__ float g_tW_h[NHd * Dd * Dd],   g_tW_l[NHd * Dd * Dd];
__device__ float g_fcWc_h[NHd * Dd * Dd], g_fcWc_l[NHd * Dd * Dd];
__device__ float g_fcWt_h[NHd * Dd * Dd], g_fcWt_l[NHd * Dd * Dd];
__device__ float g_fusW_h[Dd * Dd],     g_fusW_l[Dd * Dd];
__device__ float g_gc1W_h[Dd * H1d],    g_gc1W_l[Dd * H1d];
__device__ float g_gtext_h[Tt * Dd],    g_gtext_l[Tt * Dd];
__device__ float g_mu_h[Nn * H2d],      g_mu_l[Nn * H2d];

// ------------------------- tf32 helpers ------------------------------------
__device__ __forceinline__ void tf32_split_u(float v, uint32_t& h, uint32_t& l) {
    asm("cvt.rna.tf32.f32 %0, %1;" : "=r"(h) : "f"(v));
    float r = v - __uint_as_float(h);
    asm("cvt.rna.tf32.f32 %0, %1;" : "=r"(l) : "f"(r));
}
__device__ __forceinline__ void split_store(float v, float* hp, float* lp, size_t idx) {
    uint32_t h, l; tf32_split_u(v, h, l);
    hp[idx] = __uint_as_float(h); lp[idx] = __uint_as_float(l);
}

#define MMA_TF32(c, a, b)                                                         \
    asm volatile(                                                                  \
        "mma.sync.aligned.m16n8k8.row.col.f32.tf32.tf32.f32 "                      \
        "{%0,%1,%2,%3},{%4,%5,%6,%7},{%8,%9},{%0,%1,%2,%3};"                       \
        : "+f"((c)[0]), "+f"((c)[1]), "+f"((c)[2]), "+f"((c)[3])                   \
        : "r"((a)[0]), "r"((a)[1]), "r"((a)[2]), "r"((a)[3]),                      \
          "r"((b)[0]), "r"((b)[1]))

__device__ __forceinline__ void cp16(void* sp, const void* gp) {
    uint32_t s = (uint32_t)__cvta_generic_to_shared(sp);
    asm volatile("cp.async.cg.shared.global [%0], [%1], 16;" :: "r"(s), "l"(gp));
}

// ------------------------- split_all (weights -> hi/lo) --------------------
struct SplitJob { const float* src; float* hi; float* lo; int n4; };
struct SplitJobs6 { SplitJob j[6]; };
__global__ void split_all_kernel(SplitJobs6 jobs) {
    SplitJob jb = jobs.j[blockIdx.y];
    const float4* src = (const float4*)jb.src;
    float4* hi = (float4*)jb.hi;
    float4* lo = (float4*)jb.lo;
    for (int i = blockIdx.x * blockDim.x + threadIdx.x; i < jb.n4;
         i += gridDim.x * blockDim.x) {
        float4 v = src[i];
        uint32_t h, l;
        float4 vh, vl;
        tf32_split_u(v.x, h, l); vh.x = __uint_as_float(h); vl.x = __uint_as_float(l);
        tf32_split_u(v.y, h, l); vh.y = __uint_as_float(h); vl.y = __uint_as_float(l);
        tf32_split_u(v.z, h, l); vh.z = __uint_as_float(h); vl.z = __uint_as_float(l);
        tf32_split_u(v.w, h, l); vh.w = __uint_as_float(h); vl.w = __uint_as_float(l);
        hi[i] = vh; lo[i] = vl;
    }
}

// ------------------------- merged CSR build (both graphs) ------------------
__global__ void build_csr2_kernel(const float* __restrict__ adj,
                                  const float* __restrict__ t_adj,
                                  int* __restrict__ nbr_c, float* __restrict__ val_c,
                                  int* __restrict__ cnt_c,
                                  int* __restrict__ nbr_t, float* __restrict__ val_t,
                                  int* __restrict__ cnt_t) {
    int bi = blockIdx.x;
    const float* row;
    int n, i;
    int* nbr; float* val; int* cnt;
    if (bi < Nn) {
        i = bi; n = Nn; row = adj + (size_t)i * Nn;
        nbr = nbr_c; val = val_c; cnt = cnt_c;
    } else {
        i = bi - Nn; n = Tt; row = t_adj + (size_t)i * Tt;
        nbr = nbr_t; val = val_t; cnt = cnt_t;
    }
    int t = threadIdx.x, lane = t & 31, w = t >> 5;
    int strip = n >> 3;
    int s0 = w * strip;
    __shared__ int s_cnt[8];
    int my = 0;
    for (int b = s0; b < s0 + strip; b += 32) {
        bool p = row[b + lane] > 0.0f;
        unsigned m = __ballot_sync(0xffffffffu, p);
        my += __popc(m);
    }
    if (lane == 0) s_cnt[w] = my;
    __syncthreads();
    int off = 0;
    #pragma unroll
    for (int ww = 0; ww < 8; ww++) if (ww < w) off += s_cnt[ww];
    int tot = 0;
    #pragma unroll
    for (int ww = 0; ww < 8; ww++) tot += s_cnt[ww];
    for (int b = s0; b < s0 + strip; b += 32) {
        float v = row[b + lane];
        bool p = v > 0.0f;
        unsigned m = __ballot_sync(0xffffffffu, p);
        int pos = off + __popc(m & ((1u << lane) - 1u));
        if (p && pos < CAP) { nbr[i * CAP + pos] = b + lane; val[i * CAP + pos] = v; }
        off += __popc(m);
    }
    if (t == 0) cnt[i] = min(tot, CAP);
}

// ------------------------- GEMM core ---------------------------------------
// RA: A given as RAW fp32 (single plane, split at fragment load time).
#define BMt 128
#define BNt 64
#define BKt 16

struct ZJob {
    const float *Ah, *Al, *Bh, *Bl;
    float *C, *Ch, *Cl;
    const float* bias;
    int M, N, K, lda, ldb;
};
struct ZJobs8 { ZJob z[8]; };

template <bool TA, bool TB, bool RA>
__device__ __forceinline__ void gemm_body(
    const float* __restrict__ Ah, const float* __restrict__ Al,
    const float* __restrict__ Bh, const float* __restrict__ Bl,
    const float* __restrict__ bias, float* __restrict__ C,
    float* __restrict__ Ch, float* __restrict__ Cl,
    int M, int N, int K, int lda, int ldb, int bm, int bn) {
    constexpr int PA = RA ? 1 : 2;
    constexpr int AR = TA ? BKt : BMt;
    constexpr int AC = TA ? (BMt + 8) : (BKt + 4);
    constexpr int BR = TB ? BNt : BKt;
    constexpr int BC = TB ? (BKt + 4) : (BNt + 8);
    __shared__ float As[2][PA][AR][AC];
    __shared__ float Bs[2][2][BR][BC];

    const float* Abp[PA];
    Abp[0] = Ah;
    if (!RA) Abp[PA - 1] = Al;
    const float* Bbp[2] = { Bh, Bl };
    int t = threadIdx.x, lane = t & 31, w = t >> 5;
    int wm = (w & 3) * 32, wn = (w >> 2) * 32;
    int gid = lane >> 2, tig = lane & 3;

    float acc[2][4][4] = {};

    auto load_tile = [&](int s, int k0) {
        #pragma unroll
        for (int p = 0; p < PA; p++) {
            if (!TA) {
                #pragma unroll
                for (int j = 0; j < 2; j++) {
                    int idx = t + j * 256;
                    int row = idx >> 2;
                    int col = (idx & 3) * 4;
                    cp16(&As[s][p][row][col], Abp[p] + (size_t)(bm + row) * lda + k0 + col);
                }
            } else {
                #pragma unroll
                for (int j = 0; j < 2; j++) {
                    int idx = t + j * 256;
                    int row = idx >> 5;
                    int col = (idx & 31) * 4;
                    cp16(&As[s][p][row][col], Abp[p] + (size_t)(k0 + row) * lda + bm + col);
                }
            }
        }
        #pragma unroll
        for (int p = 0; p < 2; p++) {
            if (!TB) {
                int row = t >> 4;
                int col = (t & 15) * 4;
                cp16(&Bs[s][p][row][col], Bbp[p] + (size_t)(k0 + row) * ldb + bn + col);
            } else {
                int row = t >> 2;
                int col = (t & 3) * 4;
                cp16(&Bs[s][p][row][col], Bbp[p] + (size_t)(bn + row) * ldb + k0 + col);
            }
        }
    };

    auto Ae = [&](int s, int p, int k, int m) -> float {
        return TA ? As[s][p][k][m] : As[s][p][m][k];
    };
    auto Be = [&](int s, int p, int k, int nn) -> float {
        return TB ? Bs[s][p][nn][k] : Bs[s][p][k][nn];
    };

    int nk = K / BKt;
    load_tile(0, 0);
    asm volatile("cp.async.commit_group;");

    for (int kt = 0; kt < nk; kt++) {
        int s = kt & 1;
        if (kt + 1 < nk) {
            load_tile(s ^ 1, (kt + 1) * BKt);
            asm volatile("cp.async.commit_group;");
            asm volatile("cp.async.wait_group 1;");
        } else {
            asm volatile("cp.async.wait_group 0;");
        }
        __syncthreads();

        #pragma unroll
        for (int kk = 0; kk < BKt; kk += 8) {
            uint32_t ah[2][4], al[2][4], bh[4][2], bl[4][2];
            #pragma unroll
            for (int mt = 0; mt < 2; mt++) {
                int m0 = wm + mt * 16 + gid;
                if (RA) {
                    tf32_split_u(Ae(s, 0, kk + tig,     m0),     ah[mt][0], al[mt][0]);
                    tf32_split_u(Ae(s, 0, kk + tig,     m0 + 8), ah[mt][1], al[mt][1]);
                    tf32_split_u(Ae(s, 0, kk + tig + 4, m0),     ah[mt][2], al[mt][2]);
                    tf32_split_u(Ae(s, 0, kk + tig + 4, m0 + 8), ah[mt][3], al[mt][3]);
                } else {
                    ah[mt][0] = __float_as_uint(Ae(s, 0, kk + tig,     m0));
                    ah[mt][1] = __float_as_uint(Ae(s, 0, kk + tig,     m0 + 8));
                    ah[mt][2] = __float_as_uint(Ae(s, 0, kk + tig + 4, m0));
                    ah[mt][3] = __float_as_uint(Ae(s, 0, kk + tig + 4, m0 + 8));
                    al[mt][0] = __float_as_uint(Ae(s, PA - 1, kk + tig,     m0));
                    al[mt][1] = __float_as_uint(Ae(s, PA - 1, kk + tig,     m0 + 8));
                    al[mt][2] = __float_as_uint(Ae(s, PA - 1, kk + tig + 4, m0));
                    al[mt][3] = __float_as_uint(Ae(s, PA - 1, kk + tig + 4, m0 + 8));
                }
            }
            #pragma unroll
            for (int nt = 0; nt < 4; nt++) {
                int n0 = wn + nt * 8 + gid;
                bh[nt][0] = __float_as_uint(Be(s, 0, kk + tig,     n0));
                bh[nt][1] = __float_as_uint(Be(s, 0, kk + tig + 4, n0));
                bl[nt][0] = __float_as_uint(Be(s, 1, kk + tig,     n0));
                bl[nt][1] = __float_as_uint(Be(s, 1, kk + tig + 4, n0));
            }
            #pragma unroll
            for (int mt = 0; mt < 2; mt++)
                #pragma unroll
                for (int nt = 0; nt < 4; nt++) {
                    MMA_TF32(acc[mt][nt], al[mt], bh[nt]);
                    MMA_TF32(acc[mt][nt], ah[mt], bl[nt]);
                    MMA_TF32(acc[mt][nt], ah[mt], bh[nt]);
                }
        }
        __syncthreads();
    }

    #pragma unroll
    for (int mt = 0; mt < 2; mt++) {
        int row0 = bm + wm + mt * 16 + gid;
        #pragma unroll
        for (int nt = 0; nt < 4; nt++) {
            int col = bn + wn + nt * 8 + tig * 2;
            float bx = bias ? bias[col] : 0.0f;
            float by = bias ? bias[col + 1] : 0.0f;
            float v00 = acc[mt][nt][0] + bx, v01 = acc[mt][nt][1] + by;
            float v10 = acc[mt][nt][2] + bx, v11 = acc[mt][nt][3] + by;
            size_t i0 = (size_t)row0 * N + col;
            size_t i1 = (size_t)(row0 + 8) * N + col;
            if (C) {
                *reinterpret_cast<float2*>(&C[i0]) = make_float2(v00, v01);
                *reinterpret_cast<float2*>(&C[i1]) = make_float2(v10, v11);
            }
            if (Ch) {
                uint32_t h, l;
                float2 h0, l0, h1, l1;
                tf32_split_u(v00, h, l); h0.x = __uint_as_float(h); l0.x = __uint_as_float(l);
                tf32_split_u(v01, h, l); h0.y = __uint_as_float(h); l0.y = __uint_as_float(l);
                tf32_split_u(v10, h, l); h1.x = __uint_as_float(h); l1.x = __uint_as_float(l);
                tf32_split_u(v11, h, l); h1.y = __uint_as_float(h); l1.y = __uint_as_float(l);
                *reinterpret_cast<float2*>(&Ch[i0]) = h0;
                *reinterpret_cast<float2*>(&Cl[i0]) = l0;
                *reinterpret_cast<float2*>(&Ch[i1]) = h1;
                *reinterpret_cast<float2*>(&Cl[i1]) = l1;
            }
        }
    }
}

// single-job entry
template <bool TA, bool TB, bool RA>
__global__ void __launch_bounds__(256) mma_gemm_kernel(
    const float* __restrict__ Ah, const float* __restrict__ Al,
    const float* __restrict__ Bh, const float* __restrict__ Bl,
    const float* __restrict__ bias, float* __restrict__ C,
    float* __restrict__ Ch, float* __restrict__ Cl,
    int M, int N, int K, int lda, int ldb,
    size_t sA, size_t sB, size_t sC) {
    gemm_body<TA, TB, RA>(
        Ah + (size_t)blockIdx.z * sA, Al ? Al + (size_t)blockIdx.z * sA : nullptr,
        Bh + (size_t)blockIdx.z * sB, Bl + (size_t)blockIdx.z * sB,
        bias,
        C  ? C  + (size_t)blockIdx.z * sC : nullptr,
        Ch ? Ch + (size_t)blockIdx.z * sC : nullptr,
        Cl ? Cl + (size_t)blockIdx.z * sC : nullptr,
        M, N, K, lda, ldb,
        blockIdx.y * BMt, blockIdx.x * BNt);
}

// multi-job entry
template <bool RA>
__global__ void __launch_bounds__(256) mma_gemm_jobs_kernel(ZJobs8 jobs) {
    ZJob j = jobs.z[blockIdx.z];
    int bm = blockIdx.y * BMt, bn = blockIdx.x * BNt;
    if (bm >= j.M || bn >= j.N) return;
    gemm_body<false, false, RA>(j.Ah, j.Al, j.Bh, j.Bl, j.bias, j.C, j.Ch, j.Cl,
                                j.M, j.N, j.K, j.lda, j.ldb, bm, bn);
}

// ------------------------- split-K reduce: 4 partials -> split planes ------
__global__ void reduce4_split_kernel(const float* __restrict__ P,
                                     const float* __restrict__ bias,
                                     float* __restrict__ oh, float* __restrict__ ol,
                                     int MN4, int Ncols4) {
    int i = blockIdx.x * blockDim.x + threadIdx.x;
    if (i >= MN4) return;
    const float4* p = (const float4*)P;
    float4 a = p[i], b = p[i + MN4], c = p[i + 2 * MN4], d = p[i + 3 * MN4];
    float4 bv = ((const float4*)bias)[i % Ncols4];
    size_t base = (size_t)i * 4;
    split_store((a.x + b.x) + (c.x + d.x) + bv.x, oh, ol, base);
    split_store((a.y + b.y) + (c.y + d.y) + bv.y, oh, ol, base + 1);
    split_store((a.z + b.z) + (c.z + d.z) + bv.z, oh, ol, base + 2);
    split_store((a.w + b.w) + (c.w + d.w) + bv.w, oh, ol, base + 3);
}

// ------------- fused reduce -> RAW fused output ----------------------------
__global__ void fuse_reduce_kernel(const float* __restrict__ P0,
                                   const float* __restrict__ P2,
                                   const float* __restrict__ bias,
                                   float* __restrict__ o,
                                   int MN4, int Ncols4) {
    int i = blockIdx.x * blockDim.x + threadIdx.x;
    if (i >= MN4) return;
    const float4* p0 = (const float4*)P0;
    const float4* p2 = (const float4*)P2;
    float4 a = p0[i], b = p0[i + MN4];
    float4 c0 = p2[i], c1 = p2[i + MN4], c2 = p2[i + 2 * MN4], c3 = p2[i + 3 * MN4];
    float4 bv = ((const float4*)bias)[i % Ncols4];
    float con[4] = { a.x + b.x + bv.x, a.y + b.y + bv.y,
                     a.z + b.z + bv.z, a.w + b.w + bv.w };
    float ct[4] = { (c0.x + c1.x) + (c2.x + c3.x), (c0.y + c1.y) + (c2.y + c3.y),
                    (c0.z + c1.z) + (c2.z + c3.z), (c0.w + c1.w) + (c2.w + c3.w) };
    float4 r;
    float* rp = (float*)&r;
    #pragma unroll
    for (int u = 0; u < 4; u++) {
        float z = 1.0f / (1.0f + expf(-(con[u] + ct[u])));
        rp[u] = z * con[u] + (1.0f - z) * ct[u];
    }
    ((float4*)o)[i] = r;
}

// ------------------------- gc2 & gc3 fused SIMT GEMM -----------------------
__global__ void gc23_kernel(const float* __restrict__ A, const float* __restrict__ B2,
                            const float* __restrict__ B3, float* __restrict__ C2,
                            float* __restrict__ C3) {
    __shared__ __align__(16) float As[16][64];
    __shared__ __align__(16) float Bs[16][64];
    int bm = blockIdx.x * 64;
    int t = threadIdx.x, tx = t & 15, ty = t >> 4;
    float acc[4][4] = {};
    for (int k0 = 0; k0 < H1d; k0 += 16) {
        #pragma unroll
        for (int j = 0; j < 4; j++) {
            int li = t + j * 256;
            int r = li >> 4, c = li & 15;
            As[c][r] = A[(size_t)(bm + r) * H1d + k0 + c];
            int rb = li >> 6, cb = li & 63;
            Bs[rb][cb] = (cb < 32) ? B2[(k0 + rb) * H2d + cb]
                                   : B3[(k0 + rb) * H2d + cb - 32];
        }
        __syncthreads();
        #pragma unroll
        for (int k = 0; k < 16; k++) {
            float4 a4 = *reinterpret_cast<const float4*>(&As[k][ty << 2]);
            float4 b4 = *reinterpret_cast<const float4*>(&Bs[k][tx << 2]);
            float a[4] = {a4.x, a4.y, a4.z, a4.w};
            float b[4] = {b4.x, b4.y, b4.z, b4.w};
            #pragma unroll
            for (int u = 0; u < 4; u++)
                #pragma unroll
                for (int v = 0; v < 4; v++)
                    acc[u][v] += a[u] * b[v];
        }
        __syncthreads();
    }
    #pragma unroll
    for (int u = 0; u < 4; u++) {
        int row = bm + (ty << 2) + u;
        #pragma unroll
        for (int v = 0; v < 4; v++) {
            int col = (tx << 2) + v;
            if (col < 32) C2[(size_t)row * H2d + col] = acc[u][v];
            else          C3[(size_t)row * H2d + col - 32] = acc[u][v];
        }
    }
}

// --------- wa precompute: wa[g][v][h][din] = sum_dout W[h][din][dout]*a[h][dout]
__global__ void wa_kernel(const float* __restrict__ gat_W,
                          const float* __restrict__ gat_asrc,
                          const float* __restrict__ gat_adst,
                          const float* __restrict__ t_W,
                          const float* __restrict__ t_asrc,
                          const float* __restrict__ t_adst,
                          float* __restrict__ wa) {
    // one warp per output element group: warp computes wa[combo][din] for one din
    int gwarp = (blockIdx.x * blockDim.x + threadIdx.x) >> 5;  // 0..4095
    int lane = threadIdx.x & 31;
    if (gwarp >= 2 * 2 * NHd * Dd / Dd * Dd / 1) {}  // (bounds via grid)
    int din = gwarp & (Dd - 1);
    int combo = gwarp >> 8;           // 0..15 : [g][v][h]
    int h = combo & 3;
    int v = (combo >> 2) & 1;
    int g = combo >> 3;
    const float* W = (g == 0 ? gat_W : t_W) + (size_t)h * Dd * Dd + (size_t)din * Dd;
    const float* a = (g == 0 ? (v == 0 ? gat_asrc : gat_adst)
                             : (v == 0 ? t_asrc : t_adst)) + h * Dd;
    float acc = 0.0f;
    #pragma unroll
    for (int c = 0; c < Dd / 32; c++)
        acc += W[lane + 32 * c] * a[lane + 32 * c];
    #pragma unroll
    for (int o = 16; o; o >>= 1) acc += __shfl_down_sync(0xffffffffu, acc, o);
    if (lane == 0) wa[combo * Dd + din] = acc;
}

// --------- f/g from x: one warp per node; 8 dots sharing one x-row read ----
__global__ void fg3_kernel(const float* __restrict__ x, const float* __restrict__ t_x,
                           const float* __restrict__ wa,
                           float* __restrict__ f_c, float* __restrict__ g_c,
                           float* __restrict__ f_t, float* __restrict__ g_t) {
    int gwarp = (blockIdx.x * blockDim.x + threadIdx.x) >> 5;
    int lane = threadIdx.x & 31;
    const float* xr;
    float* f; float* g;
    int n, i;
    if (gwarp < Nn) {
        i = gwarp; n = Nn; xr = x + (size_t)i * Dd; f = f_c; g = g_c;
    } else {
        i = gwarp - Nn;
        if (i >= Tt) return;
        n = Tt; xr = t_x + (size_t)i * Dd; f = f_t; g = g_t;
    }
    int gsel = (gwarp < Nn) ? 0 : 1;
    float xv[8];
    #pragma unroll
    for (int c = 0; c < 8; c++) xv[c] = xr[lane + 32 * c];
    float acc[8] = {};
    const float* wb = wa + gsel * 8 * Dd;    // 8 combos (v,h) for this graph
    #pragma unroll
    for (int cb = 0; cb < 8; cb++) {
        const float* w = wb + cb * Dd;
        #pragma unroll
        for (int c = 0; c < 8; c++)
            acc[cb] += xv[c] * w[lane + 32 * c];
    }
    #pragma unroll
    for (int cb = 0; cb < 8; cb++) {
        float v = acc[cb];
        #pragma unroll
        for (int o = 16; o; o >>= 1) v += __shfl_down_sync(0xffffffffu, v, o);
        if (lane == 0) {
            int h = cb & 3, vv = cb >> 2;
            if (vv == 0) f[h * n + i] = v;
            else         g[h * n + i] = v;
        }
    }
}

// ------------------------- merged warp-per-(i,h) GAT attention (raw out) ---
__global__ void __launch_bounds__(256) gat_attn2_kernel(
    const float* __restrict__ Wh_c, const float* __restrict__ f_c,
    const float* __restrict__ g_c, const int* __restrict__ nbr_c,
    const int* __restrict__ cnt_c, float* __restrict__ hcatc,
    const float* __restrict__ Wh_t, const float* __restrict__ f_t,
    const float* __restrict__ g_t, const int* __restrict__ nbr_t,
    const int* __restrict__ cnt_t, float* __restrict__ hcatt) {
    int w = threadIdx.x >> 5, lane = threadIdx.x & 31;
    int gw = blockIdx.x * 8 + w;
    const float* Wh; const float* f; const float* g;
    const int* nbr; const int* cnt; float* hcat;
    int n;
    if (gw < Nn * NHd) {
        Wh = Wh_c; f = f_c; g = g_c; nbr = nbr_c; cnt = cnt_c;
        hcat = hcatc; n = Nn;
    } else {
        gw -= Nn * NHd;
        Wh = Wh_t; f = f_t; g = g_t; nbr = nbr_t; cnt = cnt_t;
        hcat = hcatt; n = Tt;
    }
    int i = gw >> 2, h = gw & 3;
    __shared__ int   sj[8][CAP];
    __shared__ float sw[8][CAP];
    int c = cnt[i];
    const int* jb = nbr + i * CAP;
    float fi = f[h * n + i];
    float m = -1e30f;
    for (int k = lane; k < c; k += 32) {
        int j = jb[k];
        sj[w][k] = j;
        float s = fi + g[h * n + j];
        s = (s >= 0.0f) ? s : LRELU_ALPHA * s;
        sw[w][k] = s;
        m = fmaxf(m, s);
    }
    #pragma unroll
    for (int o = 16; o; o >>= 1) m = fmaxf(m, __shfl_xor_sync(0xffffffffu, m, o));
    __syncwarp();
    float sum = 0.0f;
    for (int k = lane; k < c; k += 32) {
        float e = expf(sw[w][k] - m);
        sw[w][k] = e;
        sum += e;
    }
    #pragma unroll
    for (int o = 16; o; o >>= 1) sum += __shfl_xor_sync(0xffffffffu, sum, o);
    float dinv = 1.0f / sum;
    __syncwarp();
    const float* base = Wh + (size_t)h * n * Dd;
    float acc[8] = {};
    int k = 0;
    for (; k + 2 <= c; k += 2) {
        float w0 = sw[w][k], w1 = sw[w][k + 1];
        const float* r0 = base + (size_t)sj[w][k] * Dd + lane;
        const float* r1 = base + (size_t)sj[w][k + 1] * Dd + lane;
        #pragma unroll
        for (int ch = 0; ch < 8; ch++) {
            acc[ch] += w0 * __ldg(r0 + ch * 32);
            acc[ch] += w1 * __ldg(r1 + ch * 32);
        }
    }
    if (k < c) {
        float w0 = sw[w][k];
        const float* r0 = base + (size_t)sj[w][k] * Dd + lane;
        #pragma unroll
        for (int ch = 0; ch < 8; ch++) acc[ch] += w0 * __ldg(r0 + ch * 32);
    }
    size_t obase = (size_t)i * (NHd * Dd) + h * Dd + lane;
    #pragma unroll
    for (int ch = 0; ch < 8; ch++) {
        float v = acc[ch] * dinv;
        hcat[obase + ch * 32] = (v > 0.0f) ? v : expm1f(v);
    }
}

// ------------------------- sparse adj @ X, optional ReLU -------------------
__global__ void spmm_kernel(const int* __restrict__ nbr, const float* __restrict__ val,
                            const int* __restrict__ cnt, const float* __restrict__ X,
                            float* __restrict__ Y, int ncols, int do_relu) {
    int i = blockIdx.x;
    int t = threadIdx.x;
    int c = cnt[i];
    const int* jb = nbr + i * CAP;
    const float* vb = val + i * CAP;
    float a0 = 0.0f, a1 = 0.0f, a2 = 0.0f, a3 = 0.0f;
    int k = 0;
    for (; k + 4 <= c; k += 4) {
        a0 += vb[k]     * __ldg(X + (size_t)jb[k]     * ncols + t);
        a1 += vb[k + 1] * __ldg(X + (size_t)jb[k + 1] * ncols + t);
        a2 += vb[k + 2] * __ldg(X + (size_t)jb[k + 2] * ncols + t);
        a3 += vb[k + 3] * __ldg(X + (size_t)jb[k + 3] * ncols + t);
    }
    for (; k < c; k++)
        a0 += vb[k] * __ldg(X + (size_t)jb[k] * ncols + t);
    float acc = (a0 + a1) + (a2 + a3);
    if (do_relu) acc = fmaxf(acc, 0.0f);
    Y[(size_t)i * ncols + t] = acc;
}

// ------------------------- fused mu/logvar spmm ----------------------------
__global__ void spmm2_kernel(const int* __restrict__ nbr, const float* __restrict__ val,
                             const int* __restrict__ cnt, const float* __restrict__ X2,
                             const float* __restrict__ X3, float* __restrict__ mu,
                             float* __restrict__ logvar, float* __restrict__ mu_h,
                             float* __restrict__ mu_l) {
    int i = blockIdx.x;
    int t = threadIdx.x;
    int sel = t >> 5, col = t & 31;
    const float* X = sel ? X3 : X2;
    int c = cnt[i];
    const int* jb = nbr + i * CAP;
    const float* vb = val + i * CAP;
    float a0 = 0.0f, a1 = 0.0f, a2 = 0.0f, a3 = 0.0f;
    int k = 0;
    for (; k + 4 <= c; k += 4) {
        a0 += vb[k]     * __ldg(X + (size_t)jb[k]     * H2d + col);
        a1 += vb[k + 1] * __ldg(X + (size_t)jb[k + 1] * H2d + col);
        a2 += vb[k + 2] * __ldg(X + (size_t)jb[k + 2] * H2d + col);
        a3 += vb[k + 3] * __ldg(X + (size_t)jb[k + 3] * H2d + col);
    }
    for (; k < c; k++)
        a0 += vb[k] * __ldg(X + (size_t)jb[k] * H2d + col);
    float v = (a0 + a1) + (a2 + a3);
    size_t idx = (size_t)i * H2d + col;
    if (sel == 0) {
        mu[idx] = v;
        split_store(v, mu_h, mu_l, idx);
    } else {
        logvar[idx] = v;
    }
}

#define SYM(p, s) cudaGetSymbolAddress((void**)&p, s)

extern "C" void kernel_launch(void* const* d_in, const int* in_sizes, int n_in,
                              void* d_out, int out_size) {
    const float* x        = (const float*)d_in[0];
    const float* adj      = (const float*)d_in[1];
    const float* t_x      = (const float*)d_in[2];
    const float* t_adj    = (const float*)d_in[3];
    const float* tfidf    = (const float*)d_in[4];
    const float* gat_W    = (const float*)d_in[5];
    const float* gat_asrc = (const float*)d_in[6];
    const float* gat_adst = (const float*)d_in[7];
    const float* gat_fcW  = (const float*)d_in[8];
    const float* gat_fcb  = (const float*)d_in[9];
    const float* t_W      = (const float*)d_in[10];
    const float* t_asrc   = (const float*)d_in[11];
    const float* t_adst   = (const float*)d_in[12];
    const float* t_fcW    = (const float*)d_in[13];
    const float* t_fcb    = (const float*)d_in[14];
    const float* fus_W    = (const float*)d_in[15];
    const float* fus_b    = (const float*)d_in[16];
    const float* gc1_W    = (const float*)d_in[17];
    const float* gc2_W    = (const float*)d_in[18];
    const float* gc3_W    = (const float*)d_in[19];

    float* out    = (float*)d_out;
    float* mu     = out + (size_t)Nn * Nn;
    float* logvar = mu + (size_t)Nn * H2d;

    float *Wh_c, *Wh_t, *f_c, *g_c, *f_t, *g_t, *val_c, *val_t, *wa;
    float *tmp1, *h1, *tmp2a, *tmp2b, *P0, *P1, *P2;
    int *nbr_c, *cnt_c, *nbr_t, *cnt_t;
    float *gatW_h, *gatW_l, *tW_h, *tW_l, *fcWc_h, *fcWc_l, *fcWt_h, *fcWt_l;
    float *fusW_h, *fusW_l, *gc1W_h, *gc1W_l;
    float *hcatc, *hcatt, *gtext_h, *gtext_l;
    float *fused, *fusion, *mu_h, *mu_l;
    SYM(Wh_c, g_Wh_c);  SYM(Wh_t, g_Wh_t);
    SYM(f_c, g_f_c);    SYM(g_c, g_g_c);   SYM(f_t, g_f_t);  SYM(g_t, g_g_t);
    SYM(wa, g_wa);
    SYM(nbr_c, g_nbr_c); SYM(val_c, g_val_c); SYM(cnt_c, g_cnt_c);
    SYM(nbr_t, g_nbr_t); SYM(val_t, g_val_t); SYM(cnt_t, g_cnt_t);
    SYM(tmp1, g_tmp1); SYM(h1, g_h1); SYM(tmp2a, g_tmp2a); SYM(tmp2b, g_tmp2b);
    SYM(P0, g_P0); SYM(P1, g_P1); SYM(P2, g_P2);
    SYM(gatW_h, g_gatW_h); SYM(gatW_l, g_gatW_l);
    SYM(tW_h, g_tW_h);     SYM(tW_l, g_tW_l);
    SYM(fcWc_h, g_fcWc_h); SYM(fcWc_l, g_fcWc_l);
    SYM(fcWt_h, g_fcWt_h); SYM(fcWt_l, g_fcWt_l);
    SYM(fusW_h, g_fusW_h); SYM(fusW_l, g_fusW_l);
    SYM(gc1W_h, g_gc1W_h); SYM(gc1W_l, g_gc1W_l);
    SYM(hcatc, g_hcatc); SYM(hcatt, g_hcatt);
    SYM(gtext_h, g_gtext_h); SYM(gtext_l, g_gtext_l);
    SYM(fused, g_fused); SYM(fusion, g_fusion);
    SYM(mu_h, g_mu_h); SYM(mu_l, g_mu_l);

    // 0) split WEIGHTS ONLY into tf32 hi/lo planes
    {
        SplitJobs6 jobs;
        jobs.j[0] = { gat_W,   gatW_h, gatW_l, NHd * Dd * Dd / 4 };
        jobs.j[1] = { t_W,     tW_h,   tW_l,   NHd * Dd * Dd / 4 };
        jobs.j[2] = { gat_fcW, fcWc_h, fcWc_l, NHd * Dd * Dd / 4 };
        jobs.j[3] = { t_fcW,   fcWt_h, fcWt_l, NHd * Dd * Dd / 4 };
        jobs.j[4] = { fus_W,   fusW_h, fusW_l, Dd * Dd / 4 };
        jobs.j[5] = { gc1_W,   gc1W_h, gc1W_l, Dd * H1d / 4 };
        split_all_kernel<<<dim3(128, 6), 256>>>(jobs);
    }

    // 0b) wa precompute + f,g directly from x (independent of Wh GEMM)
    wa_kernel<<<(16 * Dd * 32) / 256, 256>>>(gat_W, gat_asrc, gat_adst,
                                             t_W, t_asrc, t_adst, wa);
    fg3_kernel<<<((Nn + Tt) * 32 + 255) / 256, 256>>>(x, t_x, wa, f_c, g_c, f_t, g_t);

    // 1) both adjacencies -> CSR (one launch)
    build_csr2_kernel<<<Nn + Tt, 256>>>(adj, t_adj, nbr_c, val_c, cnt_c,
                                        nbr_t, val_t, cnt_t);

    // 2) per-head Wh for BOTH graphs, ONE launch, RAW A (x / t_x)
    {
        ZJobs8 jb;
        for (int h = 0; h < NHd; h++) {
            jb.z[h] = { x, nullptr,
                        gatW_h + (size_t)h * Dd * Dd, gatW_l + (size_t)h * Dd * Dd,
                        Wh_c + (size_t)h * Nn * Dd, nullptr, nullptr, nullptr,
                        Nn, Dd, Dd, Dd, Dd };
            jb.z[NHd + h] = { t_x, nullptr,
                        tW_h + (size_t)h * Dd * Dd, tW_l + (size_t)h * Dd * Dd,
                        Wh_t + (size_t)h * Tt * Dd, nullptr, nullptr, nullptr,
                        Tt, Dd, Dd, Dd, Dd };
        }
        mma_gemm_jobs_kernel<true><<<dim3(Dd / BNt, Nn / BMt, 8), 256>>>(jb);
    }

    // 4) sparse attention + aggregation + ELU (both graphs) -> RAW hcat
    gat_attn2_kernel<<<(Nn + Tt) * NHd / 8, 256>>>(
        Wh_c, f_c, g_c, nbr_c, cnt_c, hcatc,
        Wh_t, f_t, g_t, nbr_t, cnt_t, hcatt);

    // 5) both fc GEMMs, split-K, ONE launch (6 z-jobs, RAW A = hcat)
    {
        ZJobs8 jb;
        for (int c = 0; c < 2; c++)
            jb.z[c] = { hcatc + (size_t)c * 512, nullptr,
                        fcWc_h + (size_t)c * 512 * Dd, fcWc_l + (size_t)c * 512 * Dd,
                        P0 + (size_t)c * Nn * Dd, nullptr, nullptr, nullptr,
                        Nn, Dd, 512, NHd * Dd, Dd };
        for (int c = 0; c < 4; c++)
            jb.z[2 + c] = { hcatt + (size_t)c * 256, nullptr,
                        fcWt_h + (size_t)c * 256 * Dd, fcWt_l + (size_t)c * 256 * Dd,
                        P1 + (size_t)c * Tt * Dd, nullptr, nullptr, nullptr,
                        Tt, Dd, 256, NHd * Dd, Dd };
        for (int c = 6; c < 8; c++) jb.z[c] = jb.z[0];  // unused
        mma_gemm_jobs_kernel<true><<<dim3(Dd / BNt, Nn / BMt, 6), 256>>>(jb);
    }

    // 5b) reduce fc_t partials -> gtext hi/lo (+bias)
    reduce4_split_kernel<<<(Tt * Dd / 4 + 255) / 256, 256>>>(
        P1, t_fcb, gtext_h, gtext_l, Tt * Dd / 4, Dd / 4);

    // 6) c_text = tfidf^T @ gat_text — split-K 4 x 512, RAW A (tfidf)
    {
        dim3 grid(Dd / BNt, Nn / BMt, 4);
        mma_gemm_kernel<true, false, true><<<grid, 256>>>(
            tfidf, nullptr, gtext_h, gtext_l, nullptr, P2, nullptr, nullptr,
            Nn, Dd, 512, Nn, Dd,
            (size_t)512 * Nn, (size_t)512 * Dd, (size_t)Nn * Dd);
    }

    // 7) fused reduce: concept(P0)+bias, ctext(P2), gate -> RAW fused
    fuse_reduce_kernel<<<(Nn * Dd / 4 + 255) / 256, 256>>>(
        P0, P2, gat_fcb, fused, Nn * Dd / 4, Dd / 4);

    // 7b) fusion = fused @ fus_W + fus_b  (RAW A, RAW output)
    {
        dim3 grid(Dd / BNt, Nn / BMt, 1);
        mma_gemm_kernel<false, false, true><<<grid, 256>>>(
            fused, nullptr, fusW_h, fusW_l, fus_b, fusion, nullptr, nullptr,
            Nn, Dd, Dd, Dd, Dd, 0, 0, 0);
    }

    // 8) GCN encoder (RAW A = fusion)
    {
        dim3 grid(H1d / BNt, Nn / BMt, 1);
        mma_gemm_kernel<false, false, true><<<grid, 256>>>(
            fusion, nullptr, gc1W_h, gc1W_l, nullptr, tmp1, nullptr, nullptr,
            Nn, H1d, Dd, Dd, H1d, 0, 0, 0);
    }
    spmm_kernel<<<Nn, H1d>>>(nbr_c, val_c, cnt_c, tmp1, h1, H1d, 1);

    gc23_kernel<<<Nn / 64, 256>>>(h1, gc2_W, gc3_W, tmp2a, tmp2b);
    spmm2_kernel<<<Nn, 64>>>(nbr_c, val_c, cnt_c, tmp2a, tmp2b, mu, logvar, mu_h, mu_l);

    // 9) recon = mu @ mu^T
    {
        dim3 grid(Nn / BNt, Nn / BMt, 1);
        mma_gemm_kernel<false, true, false><<<grid, 256>>>(
            mu_h, mu_l, mu_h, mu_l, nullptr, out, nullptr, nullptr,
            Nn, Nn, H2d, H2d, H2d, 0, 0, 0);
    }
}

// round 17
// speedup vs baseline: 1.0111x; 1.0111x over previous
#include <cuda_runtime.h>
#include <math.h>
#include <stdint.h>

#define Nn   4096
#define Tt   2048
#define Dd   256
#define H1d  128
#define H2d  32
#define NHd  4
#define CAP  96
#define LRELU_ALPHA 0.2f

// ------------------------- scratch (__device__ globals) --------------------
__device__ float g_Wh_c[NHd * Nn * Dd];
__device__ float g_Wh_t[NHd * Tt * Dd];
__device__ float g_f_c[NHd * Nn], g_g_c[NHd * Nn];
__device__ float g_f_t[NHd * Tt], g_g_t[NHd * Tt];
__device__ int   g_nbr_c[Nn * CAP];
__device__ float g_val_c[Nn * CAP];
__device__ int   g_cnt_c[Nn];
__device__ int   g_nbr_t[Tt * CAP];
__device__ float g_val_t[Tt * CAP];
__device__ int   g_cnt_t[Tt];
__device__ float g_tmp1[Nn * H1d];
__device__ float g_h1[Nn * H1d];
__device__ float g_tmp2a[Nn * H2d];
__device__ float g_tmp2b[Nn * H2d];
// split-K partial buffers
__device__ float g_P0[2 * Nn * Dd];
__device__ float g_P1[4 * Tt * Dd];
__device__ float g_P2[4 * Nn * Dd];
// raw intermediates (consumers split in-register)
__device__ float g_hcatc[Nn * NHd * Dd];
__device__ float g_hcatt[Tt * NHd * Dd];
__device__ float g_fused[Nn * Dd];
__device__ float g_fusion[Nn * Dd];
// hi/lo planes (weights + gtext + mu)
__device__ float g_gatW_h[NHd * Dd * Dd], g_gatW_l[NHd * Dd * Dd];
__device__ float g_tW_h[NHd * Dd * Dd],   g_tW_l[NHd * Dd * Dd];
__device__ float g_fcWc_h[NHd * Dd * Dd], g_fcWc_l[NHd * Dd * Dd];
__device__ float g_fcWt_h[NHd * Dd * Dd], g_fcWt_l[NHd * Dd * Dd];
__device__ float g_fusW_h[Dd * Dd],     g_fusW_l[Dd * Dd];
__device__ float g_gc1W_h[Dd * H1d],    g_gc1W_l[Dd * H1d];
__device__ float g_gtext_h[Tt * Dd],    g_gtext_l[Tt * Dd];
__device__ float g_mu_h[Nn * H2d],      g_mu_l[Nn * H2d];

// ------------------------- tf32 helpers ------------------------------------
__device__ __forceinline__ void tf32_split_u(float v, uint32_t& h, uint32_t& l) {
    asm("cvt.rna.tf32.f32 %0, %1;" : "=r"(h) : "f"(v));
    float r = v - __uint_as_float(h);
    asm("cvt.rna.tf32.f32 %0, %1;" : "=r"(l) : "f"(r));
}
__device__ __forceinline__ void split_store(float v, float* hp, float* lp, size_t idx) {
    uint32_t h, l; tf32_split_u(v, h, l);
    hp[idx] = __uint_as_float(h); lp[idx] = __uint_as_float(l);
}

#define MMA_TF32(c, a, b)                                                         \
    asm volatile(                                                                  \
        "mma.sync.aligned.m16n8k8.row.col.f32.tf32.tf32.f32 "                      \
        "{%0,%1,%2,%3},{%4,%5,%6,%7},{%8,%9},{%0,%1,%2,%3};"                       \
        : "+f"((c)[0]), "+f"((c)[1]), "+f"((c)[2]), "+f"((c)[3])                   \
        : "r"((a)[0]), "r"((a)[1]), "r"((a)[2]), "r"((a)[3]),                      \
          "r"((b)[0]), "r"((b)[1]))

__device__ __forceinline__ void cp16(void* sp, const void* gp) {
    uint32_t s = (uint32_t)__cvta_generic_to_shared(sp);
    asm volatile("cp.async.cg.shared.global [%0], [%1], 16;" :: "r"(s), "l"(gp));
}

// ------------------------- split_all (weights -> hi/lo) --------------------
struct SplitJob { const float* src; float* hi; float* lo; int n4; };
struct SplitJobs6 { SplitJob j[6]; };
__global__ void split_all_kernel(SplitJobs6 jobs) {
    SplitJob jb = jobs.j[blockIdx.y];
    const float4* src = (const float4*)jb.src;
    float4* hi = (float4*)jb.hi;
    float4* lo = (float4*)jb.lo;
    for (int i = blockIdx.x * blockDim.x + threadIdx.x; i < jb.n4;
         i += gridDim.x * blockDim.x) {
        float4 v = src[i];
        uint32_t h, l;
        float4 vh, vl;
        tf32_split_u(v.x, h, l); vh.x = __uint_as_float(h); vl.x = __uint_as_float(l);
        tf32_split_u(v.y, h, l); vh.y = __uint_as_float(h); vl.y = __uint_as_float(l);
        tf32_split_u(v.z, h, l); vh.z = __uint_as_float(h); vl.z = __uint_as_float(l);
        tf32_split_u(v.w, h, l); vh.w = __uint_as_float(h); vl.w = __uint_as_float(l);
        hi[i] = vh; lo[i] = vl;
    }
}

// ------------- merged CSR build (both graphs), vectorized ------------------
__global__ void build_csr2_kernel(const float* __restrict__ adj,
                                  const float* __restrict__ t_adj,
                                  int* __restrict__ nbr_c, float* __restrict__ val_c,
                                  int* __restrict__ cnt_c,
                                  int* __restrict__ nbr_t, float* __restrict__ val_t,
                                  int* __restrict__ cnt_t) {
    int bi = blockIdx.x;
    const float* row;
    int n, i;
    int* nbr; float* val; int* cnt;
    if (bi < Nn) {
        i = bi; n = Nn; row = adj + (size_t)i * Nn;
        nbr = nbr_c; val = val_c; cnt = cnt_c;
    } else {
        i = bi - Nn; n = Tt; row = t_adj + (size_t)i * Tt;
        nbr = nbr_t; val = val_t; cnt = cnt_t;
    }
    int t = threadIdx.x, lane = t & 31, w = t >> 5;
    int strip = n >> 3;            // elements per warp (multiple of 128)
    int s0 = w * strip;
    __shared__ int s_cnt[8];
    // ---- pass 1: count (float4, no ballots) ----
    int my = 0;
    for (int b = s0 + lane * 4; b < s0 + strip; b += 128) {
        float4 v = *reinterpret_cast<const float4*>(row + b);
        my += (v.x > 0.0f) + (v.y > 0.0f) + (v.z > 0.0f) + (v.w > 0.0f);
    }
    #pragma unroll
    for (int o = 16; o; o >>= 1) my += __shfl_xor_sync(0xffffffffu, my, o);
    if (lane == 0) s_cnt[w] = my;
    __syncthreads();
    int off = 0;
    #pragma unroll
    for (int ww = 0; ww < 8; ww++) if (ww < w) off += s_cnt[ww];
    int tot = 0;
    #pragma unroll
    for (int ww = 0; ww < 8; ww++) tot += s_cnt[ww];
    // ---- pass 2: ordered write (float4 + warp scan) ----
    for (int b = s0; b < s0 + strip; b += 128) {
        int base = b + lane * 4;
        float4 v = *reinterpret_cast<const float4*>(row + base);
        float vv[4] = { v.x, v.y, v.z, v.w };
        int c = (v.x > 0.0f) + (v.y > 0.0f) + (v.z > 0.0f) + (v.w > 0.0f);
        int sc = c;
        #pragma unroll
        for (int o = 1; o < 32; o <<= 1) {
            int u = __shfl_up_sync(0xffffffffu, sc, o);
            if (lane >= o) sc += u;
        }
        int pos = off + sc - c;
        #pragma unroll
        for (int u = 0; u < 4; u++) {
            if (vv[u] > 0.0f) {
                if (pos < CAP) { nbr[i * CAP + pos] = base + u; val[i * CAP + pos] = vv[u]; }
                pos++;
            }
        }
        off += __shfl_sync(0xffffffffu, sc, 31);
    }
    if (t == 0) cnt[i] = min(tot, CAP);
}

// ------------------------- GEMM core ---------------------------------------
// RA: A given as RAW fp32 (single plane, split at fragment load time).
#define BMt 128
#define BNt 64
#define BKt 16

struct ZJob {
    const float *Ah, *Al, *Bh, *Bl;
    float *C, *Ch, *Cl;
    const float* bias;
    int M, N, K, lda, ldb;
};
struct ZJobs8 { ZJob z[8]; };

template <bool TA, bool TB, bool RA>
__device__ __forceinline__ void gemm_body(
    const float* __restrict__ Ah, const float* __restrict__ Al,
    const float* __restrict__ Bh, const float* __restrict__ Bl,
    const float* __restrict__ bias, float* __restrict__ C,
    float* __restrict__ Ch, float* __restrict__ Cl,
    int M, int N, int K, int lda, int ldb, int bm, int bn) {
    constexpr int PA = RA ? 1 : 2;
    constexpr int AR = TA ? BKt : BMt;
    constexpr int AC = TA ? (BMt + 8) : (BKt + 4);
    constexpr int BR = TB ? BNt : BKt;
    constexpr int BC = TB ? (BKt + 4) : (BNt + 8);
    __shared__ float As[2][PA][AR][AC];
    __shared__ float Bs[2][2][BR][BC];

    const float* Abp[PA];
    Abp[0] = Ah;
    if (!RA) Abp[PA - 1] = Al;
    const float* Bbp[2] = { Bh, Bl };
    int t = threadIdx.x, lane = t & 31, w = t >> 5;
    int wm = (w & 3) * 32, wn = (w >> 2) * 32;
    int gid = lane >> 2, tig = lane & 3;

    float acc[2][4][4] = {};

    auto load_tile = [&](int s, int k0) {
        #pragma unroll
        for (int p = 0; p < PA; p++) {
            if (!TA) {
                #pragma unroll
                for (int j = 0; j < 2; j++) {
                    int idx = t + j * 256;
                    int row = idx >> 2;
                    int col = (idx & 3) * 4;
                    cp16(&As[s][p][row][col], Abp[p] + (size_t)(bm + row) * lda + k0 + col);
                }
            } else {
                #pragma unroll
                for (int j = 0; j < 2; j++) {
                    int idx = t + j * 256;
                    int row = idx >> 5;
                    int col = (idx & 31) * 4;
                    cp16(&As[s][p][row][col], Abp[p] + (size_t)(k0 + row) * lda + bm + col);
                }
            }
        }
        #pragma unroll
        for (int p = 0; p < 2; p++) {
            if (!TB) {
                int row = t >> 4;
                int col = (t & 15) * 4;
                cp16(&Bs[s][p][row][col], Bbp[p] + (size_t)(k0 + row) * ldb + bn + col);
            } else {
                int row = t >> 2;
                int col = (t & 3) * 4;
                cp16(&Bs[s][p][row][col], Bbp[p] + (size_t)(bn + row) * ldb + k0 + col);
            }
        }
    };

    auto Ae = [&](int s, int p, int k, int m) -> float {
        return TA ? As[s][p][k][m] : As[s][p][m][k];
    };
    auto Be = [&](int s, int p, int k, int nn) -> float {
        return TB ? Bs[s][p][nn][k] : Bs[s][p][k][nn];
    };

    int nk = K / BKt;
    load_tile(0, 0);
    asm volatile("cp.async.commit_group;");

    for (int kt = 0; kt < nk; kt++) {
        int s = kt & 1;
        if (kt + 1 < nk) {
            load_tile(s ^ 1, (kt + 1) * BKt);
            asm volatile("cp.async.commit_group;");
            asm volatile("cp.async.wait_group 1;");
        } else {
            asm volatile("cp.async.wait_group 0;");
        }
        __syncthreads();

        #pragma unroll
        for (int kk = 0; kk < BKt; kk += 8) {
            uint32_t ah[2][4], al[2][4], bh[4][2], bl[4][2];
            #pragma unroll
            for (int mt = 0; mt < 2; mt++) {
                int m0 = wm + mt * 16 + gid;
                if (RA) {
                    tf32_split_u(Ae(s, 0, kk + tig,     m0),     ah[mt][0], al[mt][0]);
                    tf32_split_u(Ae(s, 0, kk + tig,     m0 + 8), ah[mt][1], al[mt][1]);
                    tf32_split_u(Ae(s, 0, kk + tig + 4, m0),     ah[mt][2], al[mt][2]);
                    tf32_split_u(Ae(s, 0, kk + tig + 4, m0 + 8), ah[mt][3], al[mt][3]);
                } else {
                    ah[mt][0] = __float_as_uint(Ae(s, 0, kk + tig,     m0));
                    ah[mt][1] = __float_as_uint(Ae(s, 0, kk + tig,     m0 + 8));
                    ah[mt][2] = __float_as_uint(Ae(s, 0, kk + tig + 4, m0));
                    ah[mt][3] = __float_as_uint(Ae(s, 0, kk + tig + 4, m0 + 8));
                    al[mt][0] = __float_as_uint(Ae(s, PA - 1, kk + tig,     m0));
                    al[mt][1] = __float_as_uint(Ae(s, PA - 1, kk + tig,     m0 + 8));
                    al[mt][2] = __float_as_uint(Ae(s, PA - 1, kk + tig + 4, m0));
                    al[mt][3] = __float_as_uint(Ae(s, PA - 1, kk + tig + 4, m0 + 8));
                }
            }
            #pragma unroll
            for (int nt = 0; nt < 4; nt++) {
                int n0 = wn + nt * 8 + gid;
                bh[nt][0] = __float_as_uint(Be(s, 0, kk + tig,     n0));
                bh[nt][1] = __float_as_uint(Be(s, 0, kk + tig + 4, n0));
                bl[nt][0] = __float_as_uint(Be(s, 1, kk + tig,     n0));
                bl[nt][1] = __float_as_uint(Be(s, 1, kk + tig + 4, n0));
            }
            #pragma unroll
            for (int mt = 0; mt < 2; mt++)
                #pragma unroll
                for (int nt = 0; nt < 4; nt++) {
                    MMA_TF32(acc[mt][nt], al[mt], bh[nt]);
                    MMA_TF32(acc[mt][nt], ah[mt], bl[nt]);
                    MMA_TF32(acc[mt][nt], ah[mt], bh[nt]);
                }
        }
        __syncthreads();
    }

    #pragma unroll
    for (int mt = 0; mt < 2; mt++) {
        int row0 = bm + wm + mt * 16 + gid;
        #pragma unroll
        for (int nt = 0; nt < 4; nt++) {
            int col = bn + wn + nt * 8 + tig * 2;
            float bx = bias ? bias[col] : 0.0f;
            float by = bias ? bias[col + 1] : 0.0f;
            float v00 = acc[mt][nt][0] + bx, v01 = acc[mt][nt][1] + by;
            float v10 = acc[mt][nt][2] + bx, v11 = acc[mt][nt][3] + by;
            size_t i0 = (size_t)row0 * N + col;
            size_t i1 = (size_t)(row0 + 8) * N + col;
            if (C) {
                *reinterpret_cast<float2*>(&C[i0]) = make_float2(v00, v01);
                *reinterpret_cast<float2*>(&C[i1]) = make_float2(v10, v11);
            }
            if (Ch) {
                uint32_t h, l;
                float2 h0, l0, h1, l1;
                tf32_split_u(v00, h, l); h0.x = __uint_as_float(h); l0.x = __uint_as_float(l);
                tf32_split_u(v01, h, l); h0.y = __uint_as_float(h); l0.y = __uint_as_float(l);
                tf32_split_u(v10, h, l); h1.x = __uint_as_float(h); l1.x = __uint_as_float(l);
                tf32_split_u(v11, h, l); h1.y = __uint_as_float(h); l1.y = __uint_as_float(l);
                *reinterpret_cast<float2*>(&Ch[i0]) = h0;
                *reinterpret_cast<float2*>(&Cl[i0]) = l0;
                *reinterpret_cast<float2*>(&Ch[i1]) = h1;
                *reinterpret_cast<float2*>(&Cl[i1]) = l1;
            }
        }
    }
}

// single-job entry
template <bool TA, bool TB, bool RA>
__global__ void __launch_bounds__(256) mma_gemm_kernel(
    const float* __restrict__ Ah, const float* __restrict__ Al,
    const float* __restrict__ Bh, const float* __restrict__ Bl,
    const float* __restrict__ bias, float* __restrict__ C,
    float* __restrict__ Ch, float* __restrict__ Cl,
    int M, int N, int K, int lda, int ldb,
    size_t sA, size_t sB, size_t sC) {
    gemm_body<TA, TB, RA>(
        Ah + (size_t)blockIdx.z * sA, Al ? Al + (size_t)blockIdx.z * sA : nullptr,
        Bh + (size_t)blockIdx.z * sB, Bl + (size_t)blockIdx.z * sB,
        bias,
        C  ? C  + (size_t)blockIdx.z * sC : nullptr,
        Ch ? Ch + (size_t)blockIdx.z * sC : nullptr,
        Cl ? Cl + (size_t)blockIdx.z * sC : nullptr,
        M, N, K, lda, ldb,
        blockIdx.y * BMt, blockIdx.x * BNt);
}

// multi-job entry
template <bool RA>
__global__ void __launch_bounds__(256) mma_gemm_jobs_kernel(ZJobs8 jobs) {
    ZJob j = jobs.z[blockIdx.z];
    int bm = blockIdx.y * BMt, bn = blockIdx.x * BNt;
    if (bm >= j.M || bn >= j.N) return;
    gemm_body<false, false, RA>(j.Ah, j.Al, j.Bh, j.Bl, j.bias, j.C, j.Ch, j.Cl,
                                j.M, j.N, j.K, j.lda, j.ldb, bm, bn);
}

// ------------------------- split-K reduce: 4 partials -> split planes ------
__global__ void reduce4_split_kernel(const float* __restrict__ P,
                                     const float* __restrict__ bias,
                                     float* __restrict__ oh, float* __restrict__ ol,
                                     int MN4, int Ncols4) {
    int i = blockIdx.x * blockDim.x + threadIdx.x;
    if (i >= MN4) return;
    const float4* p = (const float4*)P;
    float4 a = p[i], b = p[i + MN4], c = p[i + 2 * MN4], d = p[i + 3 * MN4];
    float4 bv = ((const float4*)bias)[i % Ncols4];
    size_t base = (size_t)i * 4;
    split_store((a.x + b.x) + (c.x + d.x) + bv.x, oh, ol, base);
    split_store((a.y + b.y) + (c.y + d.y) + bv.y, oh, ol, base + 1);
    split_store((a.z + b.z) + (c.z + d.z) + bv.z, oh, ol, base + 2);
    split_store((a.w + b.w) + (c.w + d.w) + bv.w, oh, ol, base + 3);
}

// ------------- fused reduce -> RAW fused output ----------------------------
__global__ void fuse_reduce_kernel(const float* __restrict__ P0,
                                   const float* __restrict__ P2,
                                   const float* __restrict__ bias,
                                   float* __restrict__ o,
                                   int MN4, int Ncols4) {
    int i = blockIdx.x * blockDim.x + threadIdx.x;
    if (i >= MN4) return;
    const float4* p0 = (const float4*)P0;
    const float4* p2 = (const float4*)P2;
    float4 a = p0[i], b = p0[i + MN4];
    float4 c0 = p2[i], c1 = p2[i + MN4], c2 = p2[i + 2 * MN4], c3 = p2[i + 3 * MN4];
    float4 bv = ((const float4*)bias)[i % Ncols4];
    float con[4] = { a.x + b.x + bv.x, a.y + b.y + bv.y,
                     a.z + b.z + bv.z, a.w + b.w + bv.w };
    float ct[4] = { (c0.x + c1.x) + (c2.x + c3.x), (c0.y + c1.y) + (c2.y + c3.y),
                    (c0.z + c1.z) + (c2.z + c3.z), (c0.w + c1.w) + (c2.w + c3.w) };
    float4 r;
    float* rp = (float*)&r;
    #pragma unroll
    for (int u = 0; u < 4; u++) {
        float z = 1.0f / (1.0f + expf(-(con[u] + ct[u])));
        rp[u] = z * con[u] + (1.0f - z) * ct[u];
    }
    ((float4*)o)[i] = r;
}

// ------------------------- gc2 & gc3 fused SIMT GEMM -----------------------
__global__ void gc23_kernel(const float* __restrict__ A, const float* __restrict__ B2,
                            const float* __restrict__ B3, float* __restrict__ C2,
                            float* __restrict__ C3) {
    __shared__ __align__(16) float As[16][64];
    __shared__ __align__(16) float Bs[16][64];
    int bm = blockIdx.x * 64;
    int t = threadIdx.x, tx = t & 15, ty = t >> 4;
    float acc[4][4] = {};
    for (int k0 = 0; k0 < H1d; k0 += 16) {
        #pragma unroll
        for (int j = 0; j < 4; j++) {
            int li = t + j * 256;
            int r = li >> 4, c = li & 15;
            As[c][r] = A[(size_t)(bm + r) * H1d + k0 + c];
            int rb = li >> 6, cb = li & 63;
            Bs[rb][cb] = (cb < 32) ? B2[(k0 + rb) * H2d + cb]
                                   : B3[(k0 + rb) * H2d + cb - 32];
        }
        __syncthreads();
        #pragma unroll
        for (int k = 0; k < 16; k++) {
            float4 a4 = *reinterpret_cast<const float4*>(&As[k][ty << 2]);
            float4 b4 = *reinterpret_cast<const float4*>(&Bs[k][tx << 2]);
            float a[4] = {a4.x, a4.y, a4.z, a4.w};
            float b[4] = {b4.x, b4.y, b4.z, b4.w};
            #pragma unroll
            for (int u = 0; u < 4; u++)
                #pragma unroll
                for (int v = 0; v < 4; v++)
                    acc[u][v] += a[u] * b[v];
        }
        __syncthreads();
    }
    #pragma unroll
    for (int u = 0; u < 4; u++) {
        int row = bm + (ty << 2) + u;
        #pragma unroll
        for (int v = 0; v < 4; v++) {
            int col = (tx << 2) + v;
            if (col < 32) C2[(size_t)row * H2d + col] = acc[u][v];
            else          C3[(size_t)row * H2d + col - 32] = acc[u][v];
        }
    }
}

// ------------------------- merged f/g projections (R15 proven) -------------
__global__ void fg2_kernel(const float* __restrict__ Wh_c, const float* __restrict__ asrc_c,
                           const float* __restrict__ adst_c, float* __restrict__ f_c,
                           float* __restrict__ g_c,
                           const float* __restrict__ Wh_t, const float* __restrict__ asrc_t,
                           const float* __restrict__ adst_t, float* __restrict__ f_t,
                           float* __restrict__ g_t) {
    int gw = (blockIdx.x * blockDim.x + threadIdx.x) >> 5;
    int lane = threadIdx.x & 31;
    const float* Wh; const float* asrc; const float* adst; float* f; float* g;
    int n;
    if (gw < NHd * Nn) {
        Wh = Wh_c; asrc = asrc_c; adst = adst_c; f = f_c; g = g_c; n = Nn;
    } else {
        gw -= NHd * Nn;
        if (gw >= NHd * Tt) return;
        Wh = Wh_t; asrc = asrc_t; adst = adst_t; f = f_t; g = g_t; n = Tt;
    }
    int h = gw / n, i = gw - h * n;
    const float* wp = Wh + ((size_t)h * n + i) * Dd;
    const float* as = asrc + h * Dd;
    const float* ad = adst + h * Dd;
    float accf = 0.0f, accg = 0.0f;
    #pragma unroll
    for (int c = 0; c < Dd / 32; c++) {
        float v = wp[lane + 32 * c];
        accf += v * as[lane + 32 * c];
        accg += v * ad[lane + 32 * c];
    }
    #pragma unroll
    for (int o = 16; o; o >>= 1) {
        accf += __shfl_down_sync(0xffffffffu, accf, o);
        accg += __shfl_down_sync(0xffffffffu, accg, o);
    }
    if (lane == 0) { f[gw] = accf; g[gw] = accg; }
}

// ------------------------- merged warp-per-(i,h) GAT attention (raw out) ---
__global__ void __launch_bounds__(256) gat_attn2_kernel(
    const float* __restrict__ Wh_c, const float* __restrict__ f_c,
    const float* __restrict__ g_c, const int* __restrict__ nbr_c,
    const int* __restrict__ cnt_c, float* __restrict__ hcatc,
    const float* __restrict__ Wh_t, const float* __restrict__ f_t,
    const float* __restrict__ g_t, const int* __restrict__ nbr_t,
    const int* __restrict__ cnt_t, float* __restrict__ hcatt) {
    int w = threadIdx.x >> 5, lane = threadIdx.x & 31;
    int gw = blockIdx.x * 8 + w;
    const float* Wh; const float* f; const float* g;
    const int* nbr; const int* cnt; float* hcat;
    int n;
    if (gw < Nn * NHd) {
        Wh = Wh_c; f = f_c; g = g_c; nbr = nbr_c; cnt = cnt_c;
        hcat = hcatc; n = Nn;
    } else {
        gw -= Nn * NHd;
        Wh = Wh_t; f = f_t; g = g_t; nbr = nbr_t; cnt = cnt_t;
        hcat = hcatt; n = Tt;
    }
    int i = gw >> 2, h = gw & 3;
    __shared__ int   sj[8][CAP];
    __shared__ float sw[8][CAP];
    int c = cnt[i];
    const int* jb = nbr + i * CAP;
    float fi = f[h * n + i];
    float m = -1e30f;
    for (int k = lane; k < c; k += 32) {
        int j = jb[k];
        sj[w][k] = j;
        float s = fi + g[h * n + j];
        s = (s >= 0.0f) ? s : LRELU_ALPHA * s;
        sw[w][k] = s;
        m = fmaxf(m, s);
    }
    #pragma unroll
    for (int o = 16; o; o >>= 1) m = fmaxf(m, __shfl_xor_sync(0xffffffffu, m, o));
    __syncwarp();
    float sum = 0.0f;
    for (int k = lane; k < c; k += 32) {
        float e = expf(sw[w][k] - m);
        sw[w][k] = e;
        sum += e;
    }
    #pragma unroll
    for (int o = 16; o; o >>= 1) sum += __shfl_xor_sync(0xffffffffu, sum, o);
    float dinv = 1.0f / sum;
    __syncwarp();
    const float* base = Wh + (size_t)h * n * Dd;
    float acc[8] = {};
    int k = 0;
    for (; k + 2 <= c; k += 2) {
        float w0 = sw[w][k], w1 = sw[w][k + 1];
        const float* r0 = base + (size_t)sj[w][k] * Dd + lane;
        const float* r1 = base + (size_t)sj[w][k + 1] * Dd + lane;
        #pragma unroll
        for (int ch = 0; ch < 8; ch++) {
            acc[ch] += w0 * __ldg(r0 + ch * 32);
            acc[ch] += w1 * __ldg(r1 + ch * 32);
        }
    }
    if (k < c) {
        float w0 = sw[w][k];
        const float* r0 = base + (size_t)sj[w][k] * Dd + lane;
        #pragma unroll
        for (int ch = 0; ch < 8; ch++) acc[ch] += w0 * __ldg(r0 + ch * 32);
    }
    size_t obase = (size_t)i * (NHd * Dd) + h * Dd + lane;
    #pragma unroll
    for (int ch = 0; ch < 8; ch++) {
        float v = acc[ch] * dinv;
        hcat[obase + ch * 32] = (v > 0.0f) ? v : expm1f(v);
    }
}

// ------------------------- sparse adj @ X, optional ReLU -------------------
__global__ void spmm_kernel(const int* __restrict__ nbr, const float* __restrict__ val,
                            const int* __restrict__ cnt, const float* __restrict__ X,
                            float* __restrict__ Y, int ncols, int do_relu) {
    int i = blockIdx.x;
    int t = threadIdx.x;
    int c = cnt[i];
    const int* jb = nbr + i * CAP;
    const float* vb = val + i * CAP;
    float a0 = 0.0f, a1 = 0.0f, a2 = 0.0f, a3 = 0.0f;
    int k = 0;
    for (; k + 4 <= c; k += 4) {
        a0 += vb[k]     * __ldg(X + (size_t)jb[k]     * ncols + t);
        a1 += vb[k + 1] * __ldg(X + (size_t)jb[k + 1] * ncols + t);
        a2 += vb[k + 2] * __ldg(X + (size_t)jb[k + 2] * ncols + t);
        a3 += vb[k + 3] * __ldg(X + (size_t)jb[k + 3] * ncols + t);
    }
    for (; k < c; k++)
        a0 += vb[k] * __ldg(X + (size_t)jb[k] * ncols + t);
    float acc = (a0 + a1) + (a2 + a3);
    if (do_relu) acc = fmaxf(acc, 0.0f);
    Y[(size_t)i * ncols + t] = acc;
}

// ------------------------- fused mu/logvar spmm ----------------------------
__global__ void spmm2_kernel(const int* __restrict__ nbr, const float* __restrict__ val,
                             const int* __restrict__ cnt, const float* __restrict__ X2,
                             const float* __restrict__ X3, float* __restrict__ mu,
                             float* __restrict__ logvar, float* __restrict__ mu_h,
                             float* __restrict__ mu_l) {
    int i = blockIdx.x;
    int t = threadIdx.x;
    int sel = t >> 5, col = t & 31;
    const float* X = sel ? X3 : X2;
    int c = cnt[i];
    const int* jb = nbr + i * CAP;
    const float* vb = val + i * CAP;
    float a0 = 0.0f, a1 = 0.0f, a2 = 0.0f, a3 = 0.0f;
    int k = 0;
    for (; k + 4 <= c; k += 4) {
        a0 += vb[k]     * __ldg(X + (size_t)jb[k]     * H2d + col);
        a1 += vb[k + 1] * __ldg(X + (size_t)jb[k + 1] * H2d + col);
        a2 += vb[k + 2] * __ldg(X + (size_t)jb[k + 2] * H2d + col);
        a3 += vb[k + 3] * __ldg(X + (size_t)jb[k + 3] * H2d + col);
    }
    for (; k < c; k++)
        a0 += vb[k] * __ldg(X + (size_t)jb[k] * H2d + col);
    float v = (a0 + a1) + (a2 + a3);
    size_t idx = (size_t)i * H2d + col;
    if (sel == 0) {
        mu[idx] = v;
        split_store(v, mu_h, mu_l, idx);
    } else {
        logvar[idx] = v;
    }
}

#define SYM(p, s) cudaGetSymbolAddress((void**)&p, s)

extern "C" void kernel_launch(void* const* d_in, const int* in_sizes, int n_in,
                              void* d_out, int out_size) {
    const float* x        = (const float*)d_in[0];
    const float* adj      = (const float*)d_in[1];
    const float* t_x      = (const float*)d_in[2];
    const float* t_adj    = (const float*)d_in[3];
    const float* tfidf    = (const float*)d_in[4];
    const float* gat_W    = (const float*)d_in[5];
    const float* gat_asrc = (const float*)d_in[6];
    const float* gat_adst = (const float*)d_in[7];
    const float* gat_fcW  = (const float*)d_in[8];
    const float* gat_fcb  = (const float*)d_in[9];
    const float* t_W      = (const float*)d_in[10];
    const float* t_asrc   = (const float*)d_in[11];
    const float* t_adst   = (const float*)d_in[12];
    const float* t_fcW    = (const float*)d_in[13];
    const float* t_fcb    = (const float*)d_in[14];
    const float* fus_W    = (const float*)d_in[15];
    const float* fus_b    = (const float*)d_in[16];
    const float* gc1_W    = (const float*)d_in[17];
    const float* gc2_W    = (const float*)d_in[18];
    const float* gc3_W    = (const float*)d_in[19];

    float* out    = (float*)d_out;
    float* mu     = out + (size_t)Nn * Nn;
    float* logvar = mu + (size_t)Nn * H2d;

    float *Wh_c, *Wh_t, *f_c, *g_c, *f_t, *g_t, *val_c, *val_t;
    float *tmp1, *h1, *tmp2a, *tmp2b, *P0, *P1, *P2;
    int *nbr_c, *cnt_c, *nbr_t, *cnt_t;
    float *gatW_h, *gatW_l, *tW_h, *tW_l, *fcWc_h, *fcWc_l, *fcWt_h, *fcWt_l;
    float *fusW_h, *fusW_l, *gc1W_h, *gc1W_l;
    float *hcatc, *hcatt, *gtext_h, *gtext_l;
    float *fused, *fusion, *mu_h, *mu_l;
    SYM(Wh_c, g_Wh_c);  SYM(Wh_t, g_Wh_t);
    SYM(f_c, g_f_c);    SYM(g_c, g_g_c);   SYM(f_t, g_f_t);  SYM(g_t, g_g_t);
    SYM(nbr_c, g_nbr_c); SYM(val_c, g_val_c); SYM(cnt_c, g_cnt_c);
    SYM(nbr_t, g_nbr_t); SYM(val_t, g_val_t); SYM(cnt_t, g_cnt_t);
    SYM(tmp1, g_tmp1); SYM(h1, g_h1); SYM(tmp2a, g_tmp2a); SYM(tmp2b, g_tmp2b);
    SYM(P0, g_P0); SYM(P1, g_P1); SYM(P2, g_P2);
    SYM(gatW_h, g_gatW_h); SYM(gatW_l, g_gatW_l);
    SYM(tW_h, g_tW_h);     SYM(tW_l, g_tW_l);
    SYM(fcWc_h, g_fcWc_h); SYM(fcWc_l, g_fcWc_l);
    SYM(fcWt_h, g_fcWt_h); SYM(fcWt_l, g_fcWt_l);
    SYM(fusW_h, g_fusW_h); SYM(fusW_l, g_fusW_l);
    SYM(gc1W_h, g_gc1W_h); SYM(gc1W_l, g_gc1W_l);
    SYM(hcatc, g_hcatc); SYM(hcatt, g_hcatt);
    SYM(gtext_h, g_gtext_h); SYM(gtext_l, g_gtext_l);
    SYM(fused, g_fused); SYM(fusion, g_fusion);
    SYM(mu_h, g_mu_h); SYM(mu_l, g_mu_l);

    // 0) split WEIGHTS ONLY into tf32 hi/lo planes
    {
        SplitJobs6 jobs;
        jobs.j[0] = { gat_W,   gatW_h, gatW_l, NHd * Dd * Dd / 4 };
        jobs.j[1] = { t_W,     tW_h,   tW_l,   NHd * Dd * Dd / 4 };
        jobs.j[2] = { gat_fcW, fcWc_h, fcWc_l, NHd * Dd * Dd / 4 };
        jobs.j[3] = { t_fcW,   fcWt_h, fcWt_l, NHd * Dd * Dd / 4 };
        jobs.j[4] = { fus_W,   fusW_h, fusW_l, Dd * Dd / 4 };
        jobs.j[5] = { gc1_W,   gc1W_h, gc1W_l, Dd * H1d / 4 };
        split_all_kernel<<<dim3(128, 6), 256>>>(jobs);
    }

    // 1) both adjacencies -> CSR (one launch, vectorized)
    build_csr2_kernel<<<Nn + Tt, 256>>>(adj, t_adj, nbr_c, val_c, cnt_c,
                                        nbr_t, val_t, cnt_t);

    // 2) per-head Wh for BOTH graphs, ONE launch, RAW A (x / t_x)
    {
        ZJobs8 jb;
        for (int h = 0; h < NHd; h++) {
            jb.z[h] = { x, nullptr,
                        gatW_h + (size_t)h * Dd * Dd, gatW_l + (size_t)h * Dd * Dd,
                        Wh_c + (size_t)h * Nn * Dd, nullptr, nullptr, nullptr,
                        Nn, Dd, Dd, Dd, Dd };
            jb.z[NHd + h] = { t_x, nullptr,
                        tW_h + (size_t)h * Dd * Dd, tW_l + (size_t)h * Dd * Dd,
                        Wh_t + (size_t)h * Tt * Dd, nullptr, nullptr, nullptr,
                        Tt, Dd, Dd, Dd, Dd };
        }
        mma_gemm_jobs_kernel<true><<<dim3(Dd / BNt, Nn / BMt, 8), 256>>>(jb);
    }

    // 3) attention projections f,g (both graphs)
    {
        int warps = NHd * (Nn + Tt);
        fg2_kernel<<<(warps * 32 + 255) / 256, 256>>>(
            Wh_c, gat_asrc, gat_adst, f_c, g_c,
            Wh_t, t_asrc, t_adst, f_t, g_t);
    }

    // 4) sparse attention + aggregation + ELU (both graphs) -> RAW hcat
    gat_attn2_kernel<<<(Nn + Tt) * NHd / 8, 256>>>(
        Wh_c, f_c, g_c, nbr_c, cnt_c, hcatc,
        Wh_t, f_t, g_t, nbr_t, cnt_t, hcatt);

    // 5) both fc GEMMs, split-K, ONE launch (6 z-jobs, RAW A = hcat)
    {
        ZJobs8 jb;
        for (int c = 0; c < 2; c++)
            jb.z[c] = { hcatc + (size_t)c * 512, nullptr,
                        fcWc_h + (size_t)c * 512 * Dd, fcWc_l + (size_t)c * 512 * Dd,
                        P0 + (size_t)c * Nn * Dd, nullptr, nullptr, nullptr,
                        Nn, Dd, 512, NHd * Dd, Dd };
        for (int c = 0; c < 4; c++)
            jb.z[2 + c] = { hcatt + (size_t)c * 256, nullptr,
                        fcWt_h + (size_t)c * 256 * Dd, fcWt_l + (size_t)c * 256 * Dd,
                        P1 + (size_t)c * Tt * Dd, nullptr, nullptr, nullptr,
                        Tt, Dd, 256, NHd * Dd, Dd };
        for (int c = 6; c < 8; c++) jb.z[c] = jb.z[0];  // unused
        mma_gemm_jobs_kernel<true><<<dim3(Dd / BNt, Nn / BMt, 6), 256>>>(jb);
    }

    // 5b) reduce fc_t partials -> gtext hi/lo (+bias)
    reduce4_split_kernel<<<(Tt * Dd / 4 + 255) / 256, 256>>>(
        P1, t_fcb, gtext_h, gtext_l, Tt * Dd / 4, Dd / 4);

    // 6) c_text = tfidf^T @ gat_text — split-K 4 x 512, RAW A (tfidf)
    {
        dim3 grid(Dd / BNt, Nn / BMt, 4);
        mma_gemm_kernel<true, false, true><<<grid, 256>>>(
            tfidf, nullptr, gtext_h, gtext_l, nullptr, P2, nullptr, nullptr,
            Nn, Dd, 512, Nn, Dd,
            (size_t)512 * Nn, (size_t)512 * Dd, (size_t)Nn * Dd);
    }

    // 7) fused reduce: concept(P0)+bias, ctext(P2), gate -> RAW fused
    fuse_reduce_kernel<<<(Nn * Dd / 4 + 255) / 256, 256>>>(
        P0, P2, gat_fcb, fused, Nn * Dd / 4, Dd / 4);

    // 7b) fusion = fused @ fus_W + fus_b  (RAW A, RAW output)
    {
        dim3 grid(Dd / BNt, Nn / BMt, 1);
        mma_gemm_kernel<false, false, true><<<grid, 256>>>(
            fused, nullptr, fusW_h, fusW_l, fus_b, fusion, nullptr, nullptr,
            Nn, Dd, Dd, Dd, Dd, 0, 0, 0);
    }

    // 8) GCN encoder (RAW A = fusion)
    {
        dim3 grid(H1d / BNt, Nn / BMt, 1);
        mma_gemm_kernel<false, false, true><<<grid, 256>>>(
            fusion, nullptr, gc1W_h, gc1W_l, nullptr, tmp1, nullptr, nullptr,
            Nn, H1d, Dd, Dd, H1d, 0, 0, 0);
    }
    spmm_kernel<<<Nn, H1d>>>(nbr_c, val_c, cnt_c, tmp1, h1, H1d, 1);

    gc23_kernel<<<Nn / 64, 256>>>(h1, gc2_W, gc3_W, tmp2a, tmp2b);
    spmm2_kernel<<<Nn, 64>>>(nbr_c, val_c, cnt_c, tmp2a, tmp2b, mu, logvar, mu_h, mu_l);

    // 9) recon = mu @ mu^T
    {
        dim3 grid(Nn / BNt, Nn / BMt, 1);
        mma_gemm_kernel<false, true, false><<<grid, 256>>>(
            mu_h, mu_l, mu_h, mu_l, nullptr, out, nullptr, nullptr,
            Nn, Nn, H2d, H2d, H2d, 0, 0, 0);
    }
}